// round 1
// baseline (speedup 1.0000x reference)
#include <cuda_runtime.h>
#include <cuda_bf16.h>

// Problem constants
// x: (8, 512, 32, 32) fp32 ; S = 1024, HEADS=8, D=64, GROUPS=32 (16 ch/group)
#define Bn   8
#define Cn   512
#define Sn   1024
#define NH   8
#define Dh   64
#define NG   32
#define CPG  16          // channels per group
#define EPSV 1e-5f

// ---------------------------------------------------------------------------
// Static device scratch (allocation-free rule)
// ---------------------------------------------------------------------------
__device__ float g_xn   [(long)Bn * Cn * Sn];            // 16.8 MB  normalized x (b, c, s)
__device__ float g_qkv  [(long)Bn * 3 * Cn * Sn];        // 50.3 MB  (b, 3C, s)
__device__ float g_logit[(long)Bn * NH * Sn * Sn];       // 268 MB   (b*h, t, s) ; softmax in-place
__device__ float g_attn [(long)Bn * Cn * Sn];            // 16.8 MB  (b, c=h*64+d, t)
__device__ float g_mean [Bn * NG];
__device__ float g_rstd [Bn * NG];

// ---------------------------------------------------------------------------
// Block reductions
// ---------------------------------------------------------------------------
__device__ __forceinline__ float warp_sum(float v) {
    #pragma unroll
    for (int o = 16; o; o >>= 1) v += __shfl_xor_sync(0xffffffffu, v, o);
    return v;
}
__device__ __forceinline__ float warp_max(float v) {
    #pragma unroll
    for (int o = 16; o; o >>= 1) v = fmaxf(v, __shfl_xor_sync(0xffffffffu, v, o));
    return v;
}

template<bool IS_MAX>
__device__ __forceinline__ float block_reduce(float v, float* sh) {
    int lane = threadIdx.x & 31, w = threadIdx.x >> 5;
    int nw = blockDim.x >> 5;
    v = IS_MAX ? warp_max(v) : warp_sum(v);
    if (lane == 0) sh[w] = v;
    __syncthreads();
    if (w == 0) {
        float r = (lane < nw) ? sh[lane] : (IS_MAX ? -3.4e38f : 0.f);
        r = IS_MAX ? warp_max(r) : warp_sum(r);
        if (lane == 0) sh[0] = r;
    }
    __syncthreads();
    float r = sh[0];
    __syncthreads();   // safe reuse of sh by a later call
    return r;
}

// ---------------------------------------------------------------------------
// GroupNorm stats: one block per (b, g); 16*1024 = 16384 contiguous floats
// ---------------------------------------------------------------------------
__global__ void gn_stats_kernel(const float* __restrict__ x) {
    __shared__ float sh[32];
    int bg = blockIdx.x;                         // 0..255
    const float4* p = (const float4*)(x + (long)bg * (CPG * Sn));
    float s = 0.f, s2 = 0.f;
    for (int i = threadIdx.x; i < (CPG * Sn) / 4; i += blockDim.x) {
        float4 v = p[i];
        s  += v.x + v.y + v.z + v.w;
        s2 += v.x*v.x + v.y*v.y + v.z*v.z + v.w*v.w;
    }
    s  = block_reduce<false>(s,  sh);
    s2 = block_reduce<false>(s2, sh);
    if (threadIdx.x == 0) {
        float mu  = s  * (1.f / (CPG * Sn));
        float var = s2 * (1.f / (CPG * Sn)) - mu * mu;
        g_mean[bg] = mu;
        g_rstd[bg] = rsqrtf(var + EPSV);
    }
}

// ---------------------------------------------------------------------------
// GroupNorm apply: xn = (x - mu)*rstd*gamma + beta  (float4 elementwise)
// ---------------------------------------------------------------------------
__global__ void gn_apply_kernel(const float* __restrict__ x,
                                const float* __restrict__ gamma,
                                const float* __restrict__ beta) {
    long i = (long)blockIdx.x * blockDim.x + threadIdx.x;   // float4 index
    const long total4 = (long)Bn * Cn * Sn / 4;             // 1048576
    if (i >= total4) return;
    long e = i * 4;
    int c  = (int)((e >> 10) & (Cn - 1));
    int b  = (int)(e >> 19);                                // / (Cn*Sn)
    int bg = b * NG + (c >> 4);
    float mu = g_mean[bg], rs = g_rstd[bg];
    float a  = rs * gamma[c];
    float bb = beta[c] - mu * a;
    float4 v = ((const float4*)x)[i];
    float4 o;
    o.x = v.x * a + bb; o.y = v.y * a + bb;
    o.z = v.z * a + bb; o.w = v.w * a + bb;
    ((float4*)g_xn)[i] = o;
}

// ---------------------------------------------------------------------------
// Generic batched tiled SGEMM.
//   Logical: C[m,n] = alpha * sum_k A(m,k)*B(k,n) + bias[m] (+ residual)
//   A(m,k) at A[k*ldA + m] if AT else A[m*ldA + k]
//   B(k,n) at B[n*ldB + k] if BT else B[k*ldB + n]
//   Batch z: off = (z/ZH)*s?o + (z%ZH)*s?i
// All dims divide tiles for our shapes (no bounds checks needed).
// ---------------------------------------------------------------------------
template<int BM, int BN, int BK, int TM, int TN, bool AT, bool BT>
__global__ __launch_bounds__((BM/TM)*(BN/TN))
void gemm_kernel(const float* __restrict__ Ab, const float* __restrict__ Bb,
                 float* __restrict__ Cb, const float* __restrict__ Rb,
                 const float* __restrict__ bias,
                 int K, int ldA, int ldB, int ldC,
                 long sAo, long sAi, long sBo, long sBi, long sCo, long sCi,
                 int ZH, float alpha)
{
    constexpr int THREADS = (BM/TM)*(BN/TN);
    __shared__ float As[BK][BM + 1];
    __shared__ float Bs[BK][BN + 1];

    int z  = blockIdx.z;
    int zo = z / ZH, zi = z - zo * ZH;
    const float* A = Ab + zo * sAo + zi * sAi;
    const float* B = Bb + zo * sBo + zi * sBi;
    long offC = zo * sCo + zi * sCi;

    int m0 = blockIdx.y * BM, n0 = blockIdx.x * BN;
    int tid = threadIdx.x;
    int tx = tid % (BN/TN), ty = tid / (BN/TN);

    float acc[TM][TN];
    #pragma unroll
    for (int i = 0; i < TM; i++)
        #pragma unroll
        for (int j = 0; j < TN; j++) acc[i][j] = 0.f;

    for (int k0 = 0; k0 < K; k0 += BK) {
        // --- load A tile into As[k][m] ---
        if (AT) {
            #pragma unroll
            for (int r = 0; r < (BK*BM)/THREADS; r++) {
                int i = tid + r * THREADS;
                int kk = i / BM, mm = i % BM;
                As[kk][mm] = A[(long)(k0 + kk) * ldA + (m0 + mm)];
            }
        } else {
            #pragma unroll
            for (int r = 0; r < (BK*BM)/THREADS; r++) {
                int i = tid + r * THREADS;
                int mm = i / BK, kk = i % BK;
                As[kk][mm] = A[(long)(m0 + mm) * ldA + (k0 + kk)];
            }
        }
        // --- load B tile into Bs[k][n] ---
        if (BT) {
            #pragma unroll
            for (int r = 0; r < (BK*BN)/THREADS; r++) {
                int i = tid + r * THREADS;
                int nn = i / BK, kk = i % BK;
                Bs[kk][nn] = B[(long)(n0 + nn) * ldB + (k0 + kk)];
            }
        } else {
            #pragma unroll
            for (int r = 0; r < (BK*BN)/THREADS; r++) {
                int i = tid + r * THREADS;
                int kk = i / BN, nn = i % BN;
                Bs[kk][nn] = B[(long)(k0 + kk) * ldB + (n0 + nn)];
            }
        }
        __syncthreads();

        #pragma unroll
        for (int kk = 0; kk < BK; kk++) {
            float a[TM], bv[TN];
            #pragma unroll
            for (int i = 0; i < TM; i++) a[i] = As[kk][ty*TM + i];
            #pragma unroll
            for (int j = 0; j < TN; j++) bv[j] = Bs[kk][tx*TN + j];
            #pragma unroll
            for (int i = 0; i < TM; i++)
                #pragma unroll
                for (int j = 0; j < TN; j++)
                    acc[i][j] = fmaf(a[i], bv[j], acc[i][j]);
        }
        __syncthreads();
    }

    #pragma unroll
    for (int i = 0; i < TM; i++) {
        int gm = m0 + ty*TM + i;
        float bv = bias ? bias[gm] : 0.f;
        #pragma unroll
        for (int j = 0; j < TN; j++) {
            int gn = n0 + tx*TN + j;
            long ci = offC + (long)gm * ldC + gn;
            float v = acc[i][j] * alpha + bv;
            if (Rb) v += Rb[ci];
            Cb[ci] = v;
        }
    }
}

// ---------------------------------------------------------------------------
// In-place row softmax: grid = B*H*S rows, 256 threads, 1024 floats/row
// ---------------------------------------------------------------------------
__global__ void softmax_kernel(float* __restrict__ logits) {
    __shared__ float sh[8];
    long row = blockIdx.x;
    float4* p = (float4*)(logits + row * Sn);
    float4 v = p[threadIdx.x];
    float m = fmaxf(fmaxf(v.x, v.y), fmaxf(v.z, v.w));
    m = block_reduce<true>(m, sh);
    v.x = __expf(v.x - m); v.y = __expf(v.y - m);
    v.z = __expf(v.z - m); v.w = __expf(v.w - m);
    float s = v.x + v.y + v.z + v.w;
    s = block_reduce<false>(s, sh);
    float inv = 1.f / s;
    v.x *= inv; v.y *= inv; v.z *= inv; v.w *= inv;
    p[threadIdx.x] = v;
}

// ---------------------------------------------------------------------------
// Launch
// ---------------------------------------------------------------------------
extern "C" void kernel_launch(void* const* d_in, const int* in_sizes, int n_in,
                              void* d_out, int out_size) {
    const float* x      = (const float*)d_in[0];
    const float* gamma  = (const float*)d_in[1];
    const float* beta   = (const float*)d_in[2];
    const float* w_qkv  = (const float*)d_in[3];
    const float* b_qkv  = (const float*)d_in[4];
    const float* w_proj = (const float*)d_in[5];
    const float* b_proj = (const float*)d_in[6];
    float* out = (float*)d_out;

    float *xn, *qkv, *logit, *attn;
    cudaGetSymbolAddress((void**)&xn,    g_xn);
    cudaGetSymbolAddress((void**)&qkv,   g_qkv);
    cudaGetSymbolAddress((void**)&logit, g_logit);
    cudaGetSymbolAddress((void**)&attn,  g_attn);

    const long CS  = (long)Cn * Sn;          // 524288
    const long C3S = 3L * Cn * Sn;           // 1572864
    const long HS  = (long)Dh * Sn;          // 65536 (per-head channel block)
    const long SS  = (long)Sn * Sn;          // 1048576

    // 1) GroupNorm stats + apply
    gn_stats_kernel<<<Bn * NG, 256>>>(x);
    gn_apply_kernel<<<(unsigned)(Bn * Cn * Sn / 4 / 256), 256>>>(x, gamma, beta);

    // 2) QKV: (3C x C) @ xn(b: C x S)  -> qkv (b, 3C, S)   [NN]
    {
        dim3 grid(Sn/128, (3*Cn)/128, Bn);
        gemm_kernel<128,128,16,8,8,false,false><<<grid, 256>>>(
            w_qkv, xn, qkv, nullptr, b_qkv,
            /*K*/Cn, /*ldA*/Cn, /*ldB*/Sn, /*ldC*/Sn,
            0, 0, 0, CS, 0, C3S, Bn, 1.f);
    }

    // 3) logits[t,s] = 0.125 * sum_d Q(d,t) K(d,s)   [TN], batch z=b*8+h
    {
        dim3 grid(Sn/128, Sn/128, Bn * NH);
        gemm_kernel<128,128,16,8,8,true,false><<<grid, 256>>>(
            qkv /*Q base*/, qkv + CS /*K base*/, logit, nullptr, nullptr,
            /*K*/Dh, /*ldA*/Sn, /*ldB*/Sn, /*ldC*/Sn,
            C3S, HS, C3S, HS, (long)NH*SS, SS, NH, 0.125f);
    }

    // 4) softmax in place over last dim
    softmax_kernel<<<(unsigned)(Bn * NH * Sn), 256>>>(logit);

    // 5) attn_out[d,t] = sum_s V(d,s) P(t,s)   [NT] -> g_attn (b, h*64+d, t)
    {
        dim3 grid(Sn/128, Dh/64, Bn * NH);
        gemm_kernel<64,128,16,4,8,false,true><<<grid, 256>>>(
            qkv + 2*CS /*V base*/, logit /*P*/, attn, nullptr, nullptr,
            /*K*/Sn, /*ldA*/Sn, /*ldB*/Sn, /*ldC*/Sn,
            C3S, HS, (long)NH*SS, SS, CS, HS, NH, 1.f);
    }

    // 6) proj: (C x C) @ attn(b: C x S) + bias + residual(x) -> out  [NN]
    {
        dim3 grid(Sn/128, Cn/128, Bn);
        gemm_kernel<128,128,16,8,8,false,false><<<grid, 256>>>(
            w_proj, attn, out, x /*residual*/, b_proj,
            /*K*/Cn, /*ldA*/Cn, /*ldB*/Sn, /*ldC*/Sn,
            0, 0, 0, CS, 0, CS, Bn, 1.f);
    }
}

// round 2
// speedup vs baseline: 1.0527x; 1.0527x over previous
#include <cuda_runtime.h>
#include <cuda_bf16.h>

// Problem constants
// x: (8, 512, 32, 32) fp32 ; S = 1024, HEADS=8, D=64, GROUPS=32 (16 ch/group)
#define Bn   8
#define Cn   512
#define Sn   1024
#define NH   8
#define Dh   64
#define NG   32
#define CPG  16          // channels per group
#define EPSV 1e-5f

// ---------------------------------------------------------------------------
// Static device scratch (allocation-free rule)
// ---------------------------------------------------------------------------
__device__ float g_xn   [(long)Bn * Cn * Sn];            // 16.8 MB  normalized x (b, c, s)
__device__ float g_qkv  [(long)Bn * 3 * Cn * Sn];        // 50.3 MB  (b, 3C, s)
__device__ float g_logit[(long)Bn * NH * Sn * Sn];       // 268 MB   (b*h, t, s) ; softmax in-place
__device__ float g_attn [(long)Bn * Cn * Sn];            // 16.8 MB  (b, c=h*64+d, t)
__device__ float g_mean [Bn * NG];
__device__ float g_rstd [Bn * NG];

// ---------------------------------------------------------------------------
// Block reductions
// ---------------------------------------------------------------------------
__device__ __forceinline__ float warp_sum(float v) {
    #pragma unroll
    for (int o = 16; o; o >>= 1) v += __shfl_xor_sync(0xffffffffu, v, o);
    return v;
}
__device__ __forceinline__ float warp_max(float v) {
    #pragma unroll
    for (int o = 16; o; o >>= 1) v = fmaxf(v, __shfl_xor_sync(0xffffffffu, v, o));
    return v;
}

template<bool IS_MAX>
__device__ __forceinline__ float block_reduce(float v, float* sh) {
    int lane = threadIdx.x & 31, w = threadIdx.x >> 5;
    int nw = blockDim.x >> 5;
    v = IS_MAX ? warp_max(v) : warp_sum(v);
    if (lane == 0) sh[w] = v;
    __syncthreads();
    if (w == 0) {
        float r = (lane < nw) ? sh[lane] : (IS_MAX ? -3.4e38f : 0.f);
        r = IS_MAX ? warp_max(r) : warp_sum(r);
        if (lane == 0) sh[0] = r;
    }
    __syncthreads();
    float r = sh[0];
    __syncthreads();   // safe reuse of sh by a later call
    return r;
}

// ---------------------------------------------------------------------------
// GroupNorm stats: one block per (b, g); 16*1024 = 16384 contiguous floats
// ---------------------------------------------------------------------------
__global__ void gn_stats_kernel(const float* __restrict__ x) {
    __shared__ float sh[32];
    int bg = blockIdx.x;                         // 0..255
    const float4* p = (const float4*)(x + (long)bg * (CPG * Sn));
    float s = 0.f, s2 = 0.f;
    for (int i = threadIdx.x; i < (CPG * Sn) / 4; i += blockDim.x) {
        float4 v = p[i];
        s  += v.x + v.y + v.z + v.w;
        s2 += v.x*v.x + v.y*v.y + v.z*v.z + v.w*v.w;
    }
    s  = block_reduce<false>(s,  sh);
    s2 = block_reduce<false>(s2, sh);
    if (threadIdx.x == 0) {
        float mu  = s  * (1.f / (CPG * Sn));
        float var = s2 * (1.f / (CPG * Sn)) - mu * mu;
        g_mean[bg] = mu;
        g_rstd[bg] = rsqrtf(var + EPSV);
    }
}

// ---------------------------------------------------------------------------
// GroupNorm apply: xn = (x - mu)*rstd*gamma + beta  (float4 elementwise)
// ---------------------------------------------------------------------------
__global__ void gn_apply_kernel(const float* __restrict__ x,
                                const float* __restrict__ gamma,
                                const float* __restrict__ beta) {
    long i = (long)blockIdx.x * blockDim.x + threadIdx.x;   // float4 index
    const long total4 = (long)Bn * Cn * Sn / 4;             // 1048576
    if (i >= total4) return;
    long e = i * 4;
    int c  = (int)((e >> 10) & (Cn - 1));
    int b  = (int)(e >> 19);                                // / (Cn*Sn)
    int bg = b * NG + (c >> 4);
    float mu = g_mean[bg], rs = g_rstd[bg];
    float a  = rs * gamma[c];
    float bb = beta[c] - mu * a;
    float4 v = ((const float4*)x)[i];
    float4 o;
    o.x = v.x * a + bb; o.y = v.y * a + bb;
    o.z = v.z * a + bb; o.w = v.w * a + bb;
    ((float4*)g_xn)[i] = o;
}

// ---------------------------------------------------------------------------
// Generic batched tiled SGEMM.
//   Logical: C[m,n] = alpha * sum_k A(m,k)*B(k,n) + bias[m] (+ residual)
//   A(m,k) at A[k*ldA + m] if AT else A[m*ldA + k]
//   B(k,n) at B[n*ldB + k] if BT else B[k*ldB + n]
//   Batch z: off = (z/ZH)*s?o + (z%ZH)*s?i
// All dims divide tiles for our shapes (no bounds checks needed).
// ---------------------------------------------------------------------------
template<int BM, int BN, int BK, int TM, int TN, bool AT, bool BT>
__global__ __launch_bounds__((BM/TM)*(BN/TN))
void gemm_kernel(const float* __restrict__ Ab, const float* __restrict__ Bb,
                 float* __restrict__ Cb, const float* __restrict__ Rb,
                 const float* __restrict__ bias,
                 int K, int ldA, int ldB, int ldC,
                 long sAo, long sAi, long sBo, long sBi, long sCo, long sCi,
                 int ZH, float alpha)
{
    constexpr int THREADS = (BM/TM)*(BN/TN);
    __shared__ float As[BK][BM + 1];
    __shared__ float Bs[BK][BN + 1];

    int z  = blockIdx.z;
    int zo = z / ZH, zi = z - zo * ZH;
    const float* A = Ab + zo * sAo + zi * sAi;
    const float* B = Bb + zo * sBo + zi * sBi;
    long offC = zo * sCo + zi * sCi;

    int m0 = blockIdx.y * BM, n0 = blockIdx.x * BN;
    int tid = threadIdx.x;
    int tx = tid % (BN/TN), ty = tid / (BN/TN);

    float acc[TM][TN];
    #pragma unroll
    for (int i = 0; i < TM; i++)
        #pragma unroll
        for (int j = 0; j < TN; j++) acc[i][j] = 0.f;

    for (int k0 = 0; k0 < K; k0 += BK) {
        // --- load A tile into As[k][m] ---
        if (AT) {
            #pragma unroll
            for (int r = 0; r < (BK*BM)/THREADS; r++) {
                int i = tid + r * THREADS;
                int kk = i / BM, mm = i % BM;
                As[kk][mm] = A[(long)(k0 + kk) * ldA + (m0 + mm)];
            }
        } else {
            #pragma unroll
            for (int r = 0; r < (BK*BM)/THREADS; r++) {
                int i = tid + r * THREADS;
                int mm = i / BK, kk = i % BK;
                As[kk][mm] = A[(long)(m0 + mm) * ldA + (k0 + kk)];
            }
        }
        // --- load B tile into Bs[k][n] ---
        if (BT) {
            #pragma unroll
            for (int r = 0; r < (BK*BN)/THREADS; r++) {
                int i = tid + r * THREADS;
                int nn = i / BK, kk = i % BK;
                Bs[kk][nn] = B[(long)(n0 + nn) * ldB + (k0 + kk)];
            }
        } else {
            #pragma unroll
            for (int r = 0; r < (BK*BN)/THREADS; r++) {
                int i = tid + r * THREADS;
                int kk = i / BN, nn = i % BN;
                Bs[kk][nn] = B[(long)(k0 + kk) * ldB + (n0 + nn)];
            }
        }
        __syncthreads();

        #pragma unroll
        for (int kk = 0; kk < BK; kk++) {
            float a[TM], bv[TN];
            #pragma unroll
            for (int i = 0; i < TM; i++) a[i] = As[kk][ty*TM + i];
            #pragma unroll
            for (int j = 0; j < TN; j++) bv[j] = Bs[kk][tx*TN + j];
            #pragma unroll
            for (int i = 0; i < TM; i++)
                #pragma unroll
                for (int j = 0; j < TN; j++)
                    acc[i][j] = fmaf(a[i], bv[j], acc[i][j]);
        }
        __syncthreads();
    }

    #pragma unroll
    for (int i = 0; i < TM; i++) {
        int gm = m0 + ty*TM + i;
        float bv = bias ? bias[gm] : 0.f;
        #pragma unroll
        for (int j = 0; j < TN; j++) {
            int gn = n0 + tx*TN + j;
            long ci = offC + (long)gm * ldC + gn;
            float v = acc[i][j] * alpha + bv;
            if (Rb) v += Rb[ci];
            Cb[ci] = v;
        }
    }
}

// ---------------------------------------------------------------------------
// In-place row softmax: grid = B*H*S rows, 256 threads, 1024 floats/row
// ---------------------------------------------------------------------------
__global__ void softmax_kernel(float* __restrict__ logits) {
    __shared__ float sh[8];
    long row = blockIdx.x;
    float4* p = (float4*)(logits + row * Sn);
    float4 v = p[threadIdx.x];
    float m = fmaxf(fmaxf(v.x, v.y), fmaxf(v.z, v.w));
    m = block_reduce<true>(m, sh);
    v.x = __expf(v.x - m); v.y = __expf(v.y - m);
    v.z = __expf(v.z - m); v.w = __expf(v.w - m);
    float s = v.x + v.y + v.z + v.w;
    s = block_reduce<false>(s, sh);
    float inv = 1.f / s;
    v.x *= inv; v.y *= inv; v.z *= inv; v.w *= inv;
    p[threadIdx.x] = v;
}

// ---------------------------------------------------------------------------
// Launch
// ---------------------------------------------------------------------------
extern "C" void kernel_launch(void* const* d_in, const int* in_sizes, int n_in,
                              void* d_out, int out_size) {
    const float* x      = (const float*)d_in[0];
    const float* gamma  = (const float*)d_in[1];
    const float* beta   = (const float*)d_in[2];
    const float* w_qkv  = (const float*)d_in[3];
    const float* b_qkv  = (const float*)d_in[4];
    const float* w_proj = (const float*)d_in[5];
    const float* b_proj = (const float*)d_in[6];
    float* out = (float*)d_out;

    float *xn, *qkv, *logit, *attn;
    cudaGetSymbolAddress((void**)&xn,    g_xn);
    cudaGetSymbolAddress((void**)&qkv,   g_qkv);
    cudaGetSymbolAddress((void**)&logit, g_logit);
    cudaGetSymbolAddress((void**)&attn,  g_attn);

    const long CS  = (long)Cn * Sn;          // 524288
    const long C3S = 3L * Cn * Sn;           // 1572864
    const long HS  = (long)Dh * Sn;          // 65536 (per-head channel block)
    const long SS  = (long)Sn * Sn;          // 1048576

    // 1) GroupNorm stats + apply
    gn_stats_kernel<<<Bn * NG, 256>>>(x);
    gn_apply_kernel<<<(unsigned)(Bn * Cn * Sn / 4 / 256), 256>>>(x, gamma, beta);

    // 2) QKV: (3C x C) @ xn(b: C x S)  -> qkv (b, 3C, S)   [NN]
    {
        dim3 grid(Sn/128, (3*Cn)/128, Bn);
        gemm_kernel<128,128,16,8,8,false,false><<<grid, 256>>>(
            w_qkv, xn, qkv, nullptr, b_qkv,
            /*K*/Cn, /*ldA*/Cn, /*ldB*/Sn, /*ldC*/Sn,
            0, 0, 0, CS, 0, C3S, Bn, 1.f);
    }

    // 3) logits[t,s] = 0.125 * sum_d Q(d,t) K(d,s)   [TN], batch z=b*8+h
    {
        dim3 grid(Sn/128, Sn/128, Bn * NH);
        gemm_kernel<128,128,16,8,8,true,false><<<grid, 256>>>(
            qkv /*Q base*/, qkv + CS /*K base*/, logit, nullptr, nullptr,
            /*K*/Dh, /*ldA*/Sn, /*ldB*/Sn, /*ldC*/Sn,
            C3S, HS, C3S, HS, (long)NH*SS, SS, NH, 0.125f);
    }

    // 4) softmax in place over last dim
    softmax_kernel<<<(unsigned)(Bn * NH * Sn), 256>>>(logit);

    // 5) attn_out[d,t] = sum_s V(d,s) P(t,s)   [NT] -> g_attn (b, h*64+d, t)
    {
        dim3 grid(Sn/128, Dh/64, Bn * NH);
        gemm_kernel<64,128,16,4,8,false,true><<<grid, 256>>>(
            qkv + 2*CS /*V base*/, logit /*P*/, attn, nullptr, nullptr,
            /*K*/Sn, /*ldA*/Sn, /*ldB*/Sn, /*ldC*/Sn,
            C3S, HS, (long)NH*SS, SS, CS, HS, NH, 1.f);
    }

    // 6) proj: (C x C) @ attn(b: C x S) + bias + residual(x) -> out  [NN]
    {
        dim3 grid(Sn/128, Cn/128, Bn);
        gemm_kernel<128,128,16,8,8,false,false><<<grid, 256>>>(
            w_proj, attn, out, x /*residual*/, b_proj,
            /*K*/Cn, /*ldA*/Cn, /*ldB*/Sn, /*ldC*/Sn,
            0, 0, 0, CS, 0, CS, Bn, 1.f);
    }
}

// round 4
// speedup vs baseline: 3.2608x; 3.0975x over previous
#include <cuda_runtime.h>
#include <cuda_bf16.h>
#include <cuda_fp16.h>
#include <cstdint>

#define Bn 8
#define Cn 512
#define Sn 1024
#define NH 8
#define NG 32
#define EPSV 1e-5f

// ---------------------------------------------------------------------------
// Static device scratch (allocation-free rule)
// ---------------------------------------------------------------------------
__device__ float g_xnT  [(long)Bn * Sn * Cn];        // (b, s, c)   16.8 MB
__device__ float g_q    [(long)Bn * NH * Sn * 64];   // (bh, t, d)  16.8 MB
__device__ float g_k    [(long)Bn * NH * Sn * 64];   // (bh, s, d)
__device__ float g_v    [(long)Bn * NH * 64 * Sn];   // (bh, d, s)
__device__ float g_logit[(long)Bn * NH * Sn * Sn];   // (bh, t, s)  268 MB
__device__ float g_hT   [(long)Bn * Sn * Cn];        // (b, t, c)   16.8 MB
__device__ float g_mean [Bn * NG];
__device__ float g_rstd [Bn * NG];

// ---------------------------------------------------------------------------
// PTX helpers (base ISA only: ldmatrix + mma.sync, supported on compute_103)
// ---------------------------------------------------------------------------
__device__ __forceinline__ uint32_t smem_u32(const void* p) {
    uint32_t a;
    asm("{ .reg .u64 t; cvta.to.shared.u64 t, %1; cvt.u32.u64 %0, t; }" : "=r"(a) : "l"(p));
    return a;
}
__device__ __forceinline__ void ldsm4(uint32_t* r, uint32_t addr) {
    asm volatile("ldmatrix.sync.aligned.m8n8.x4.shared.b16 {%0,%1,%2,%3}, [%4];"
        : "=r"(r[0]), "=r"(r[1]), "=r"(r[2]), "=r"(r[3]) : "r"(addr));
}
__device__ __forceinline__ void mma16816(float* c, const uint32_t* a, const uint32_t* b) {
    asm volatile("mma.sync.aligned.m16n8k16.row.col.f32.f16.f16.f32 "
        "{%0,%1,%2,%3}, {%4,%5,%6,%7}, {%8,%9}, {%0,%1,%2,%3};"
        : "+f"(c[0]), "+f"(c[1]), "+f"(c[2]), "+f"(c[3])
        : "r"(a[0]), "r"(a[1]), "r"(a[2]), "r"(a[3]), "r"(b[0]), "r"(b[1]));
}
__device__ __forceinline__ uint32_t packh2(float a, float b) {
    __half2 t = __floats2half2_rn(a, b);
    return *reinterpret_cast<uint32_t*>(&t);
}
#define SWZ(o) ((o) ^ (((o) >> 3) & 0x70))

// ---------------------------------------------------------------------------
// Tile loader: [ROWS x 64] fp32 -> fp16 hi/lo tiles, SW128-swizzled.
// Row = 64 halfs = 128 bytes (one swizzle atom row).
// ---------------------------------------------------------------------------
template<int ROWS>
__device__ __forceinline__ void load_tile(char* hiT, char* loT,
        const float* __restrict__ src, long ld, int r0, int k0, int tid) {
    #pragma unroll
    for (int it = 0; it < ROWS / 16; it++) {    // ROWS*16 float4s / 256 threads
        int idx = it * 256 + tid;
        int row = idx >> 4;
        int k4  = (idx & 15) << 2;              // fp32 k offset
        float4 v = *(const float4*)(src + (long)(r0 + row) * ld + k0 + k4);
        __half2 h0 = __floats2half2_rn(v.x, v.y);
        __half2 h1 = __floats2half2_rn(v.z, v.w);
        float2 f0 = __half22float2(h0), f1 = __half22float2(h1);
        uint2 hi = make_uint2(*reinterpret_cast<uint32_t*>(&h0),
                              *reinterpret_cast<uint32_t*>(&h1));
        uint2 lo = make_uint2(packh2(v.x - f0.x, v.y - f0.y),
                              packh2(v.z - f1.x, v.w - f1.y));
        uint32_t off = (uint32_t)row * 128u + (uint32_t)k4 * 2u;
        uint32_t sw = SWZ(off);
        *reinterpret_cast<uint2*>(hiT + sw) = hi;
        *reinterpret_cast<uint2*>(loT + sw) = lo;
    }
}

// ---------------------------------------------------------------------------
// HMMA GEMM:  D[m,n] = alpha * sum_k A[m,k]*B[n,k]   (both K-major fp32)
//   fp16x3: D = Ahi*Bhi + Alo*Bhi + Ahi*Blo  (fp32 accum)
// MODE 0: QKV scatter (Out=q, O2=k, O3=v, bias=b_qkv), z=b
// MODE 1: logits (Out=g_logit), z=bh
// MODE 2: attn -> hT (Out=g_hT), z=bh, BN=64
// MODE 3: proj (+bias +residual) -> out, z=b
// ---------------------------------------------------------------------------
template<int BM, int BN, int MODE>
__global__ __launch_bounds__(256)
void mma_gemm(const float* __restrict__ A, long ldA, long Az,
              const float* __restrict__ Bp, long ldB, long Bz,
              int K, const float* __restrict__ bias, const float* __restrict__ resid,
              float* __restrict__ Out, float* __restrict__ O2, float* __restrict__ O3,
              float alpha)
{
    extern __shared__ char smraw[];
    uint32_t sb = smem_u32(smraw);
    uint32_t aB = (sb + 1023u) & ~1023u;
    char* base = smraw + (aB - sb);
    char* aHi = base;
    char* aLo = base + BM * 128;
    char* bHi = base + 2 * BM * 128;
    char* bLo = bHi + BN * 128;
    uint32_t aHiU = aB, aLoU = aB + BM * 128;
    uint32_t bHiU = aB + 2 * BM * 128, bLoU = bHiU + BN * 128;
    float* stage = (float*)base;                    // overlays tiles after mma

    constexpr int WNT = BN / 4;                     // warp n-tile: 32 or 16
    constexpr int NI  = WNT / 8;                    // n8 frags per warp: 4 or 2
    constexpr int NG4 = NI / 2;                     // n16 ldmatrix groups

    int tid = threadIdx.x, wid = tid >> 5, lane = tid & 31;
    int wm = wid >> 2, wn = wid & 3;
    int m0 = blockIdx.y * BM, n0 = blockIdx.x * BN, z = blockIdx.z;
    const float* Ab = A  + (long)z * Az;
    const float* Bb = Bp + (long)z * Bz;

    float acc[4][NI][4];
    #pragma unroll
    for (int mi = 0; mi < 4; mi++)
        #pragma unroll
        for (int ni = 0; ni < NI; ni++)
            #pragma unroll
            for (int j = 0; j < 4; j++) acc[mi][ni][j] = 0.f;

    int nPass = K >> 6;
    for (int pass = 0; pass < nPass; ++pass) {
        int k0 = pass << 6;
        load_tile<BM>(aHi, aLo, Ab, ldA, m0, k0, tid);
        load_tile<BN>(bHi, bLo, Bb, ldB, n0, k0, tid);
        __syncthreads();

        #pragma unroll
        for (int kc = 0; kc < 4; kc++) {
            uint32_t ah[4][4], al[4][4], bh[NI][2], bl[NI][2];
            #pragma unroll
            for (int mi = 0; mi < 4; mi++) {
                int row = wm * 64 + mi * 16 + (lane & 15);
                uint32_t off = (uint32_t)row * 128u + kc * 32u + ((lane >> 4) << 4);
                uint32_t sw = SWZ(off);
                ldsm4(ah[mi], aHiU + sw);
                ldsm4(al[mi], aLoU + sw);
            }
            #pragma unroll
            for (int g = 0; g < NG4; g++) {
                int nr = wn * WNT + g * 16 + (lane & 7) + ((lane >> 4) & 1) * 8;
                uint32_t off = (uint32_t)nr * 128u + kc * 32u + (((lane >> 3) & 1) << 4);
                uint32_t sw = SWZ(off);
                uint32_t t4[4];
                ldsm4(t4, bHiU + sw);
                bh[g*2][0] = t4[0]; bh[g*2][1] = t4[1];
                bh[g*2+1][0] = t4[2]; bh[g*2+1][1] = t4[3];
                ldsm4(t4, bLoU + sw);
                bl[g*2][0] = t4[0]; bl[g*2][1] = t4[1];
                bl[g*2+1][0] = t4[2]; bl[g*2+1][1] = t4[3];
            }
            #pragma unroll
            for (int mi = 0; mi < 4; mi++)
                #pragma unroll
                for (int ni = 0; ni < NI; ni++) {
                    mma16816(acc[mi][ni], ah[mi], bh[ni]);
                    mma16816(acc[mi][ni], al[mi], bh[ni]);
                    mma16816(acc[mi][ni], ah[mi], bl[ni]);
                }
        }
        __syncthreads();
    }

    // ---- stage accumulators through SMEM (coalesced layout transforms) ----
    constexpr int SLD = BN + 2;
    #pragma unroll
    for (int mi = 0; mi < 4; mi++)
        #pragma unroll
        for (int ni = 0; ni < NI; ni++) {
            int r = wm * 64 + mi * 16 + (lane >> 2);
            int c = wn * WNT + ni * 8 + (lane & 3) * 2;
            *(float2*)&stage[r * SLD + c] =
                make_float2(acc[mi][ni][0] * alpha, acc[mi][ni][1] * alpha);
            *(float2*)&stage[(r + 8) * SLD + c] =
                make_float2(acc[mi][ni][2] * alpha, acc[mi][ni][3] * alpha);
        }
    __syncthreads();

    if (MODE == 0) {
        int three = m0 >> 9;
        int b = z;
        if (three < 2) {
            float* dst = (three == 0) ? Out : O2;
            for (int cc = wid; cc < BN; cc += 8) {
                int t = n0 + cc;
                #pragma unroll
                for (int ii = 0; ii < BM / 32; ii++) {
                    int r = lane + 32 * ii;
                    int o = (m0 + r) & 511;
                    int h = o >> 6, d = o & 63;
                    dst[(((long)(b * 8 + h) << 10) + t) * 64 + d] =
                        stage[r * SLD + cc] + bias[m0 + r];
                }
            }
        } else {
            for (int r = wid; r < BM; r += 8) {
                int o = (m0 + r) & 511;
                int h = o >> 6, d = o & 63;
                float bv = bias[m0 + r];
                long basei = ((long)(b * 8 + h) * 64 + d) * 1024 + n0;
                #pragma unroll
                for (int j = 0; j < BN / 32; j++) {
                    int c = lane + 32 * j;
                    O3[basei + c] = stage[r * SLD + c] + bv;
                }
            }
        }
    } else if (MODE == 1) {
        for (int r = wid; r < BM; r += 8) {
            long basei = (long)z * 1048576 + (long)(m0 + r) * 1024 + n0;
            #pragma unroll
            for (int j = 0; j < BN / 32; j++) {
                int c = lane + 32 * j;
                Out[basei + c] = stage[r * SLD + c];
            }
        }
    } else if (MODE == 2) {
        int b = z >> 3, h = z & 7;
        for (int r = wid; r < BM; r += 8) {
            long basei = ((long)(b * 1024 + m0 + r)) * 512 + h * 64;
            #pragma unroll
            for (int j = 0; j < BN / 32; j++) {
                int c = lane + 32 * j;
                Out[basei + c] = stage[r * SLD + c];
            }
        }
    } else {
        for (int r = wid; r < BM; r += 8) {
            int o = m0 + r;
            float bv = bias[o];
            long basei = (long)z * 524288 + (long)o * 1024 + n0;
            #pragma unroll
            for (int j = 0; j < BN / 32; j++) {
                int c = lane + 32 * j;
                Out[basei + c] = stage[r * SLD + c] + bv + resid[basei + c];
            }
        }
    }
}

// ---------------------------------------------------------------------------
// Reductions, GroupNorm, softmax
// ---------------------------------------------------------------------------
__device__ __forceinline__ float warp_sum(float v) {
    #pragma unroll
    for (int o = 16; o; o >>= 1) v += __shfl_xor_sync(0xffffffffu, v, o);
    return v;
}
__device__ __forceinline__ float warp_max(float v) {
    #pragma unroll
    for (int o = 16; o; o >>= 1) v = fmaxf(v, __shfl_xor_sync(0xffffffffu, v, o));
    return v;
}
template<bool ISMAX>
__device__ __forceinline__ float block_reduce(float v, float* sh) {
    int lane = threadIdx.x & 31, w = threadIdx.x >> 5, nw = blockDim.x >> 5;
    v = ISMAX ? warp_max(v) : warp_sum(v);
    if (lane == 0) sh[w] = v;
    __syncthreads();
    if (w == 0) {
        float r = (lane < nw) ? sh[lane] : (ISMAX ? -3.4e38f : 0.f);
        r = ISMAX ? warp_max(r) : warp_sum(r);
        if (lane == 0) sh[0] = r;
    }
    __syncthreads();
    float r = sh[0];
    __syncthreads();
    return r;
}

__global__ void gn_stats_kernel(const float* __restrict__ x) {
    __shared__ float sh[32];
    int bg = blockIdx.x;
    const float4* p = (const float4*)(x + (long)bg * 16384);
    float s = 0.f, s2 = 0.f;
    for (int i = threadIdx.x; i < 4096; i += blockDim.x) {
        float4 v = p[i];
        s  += v.x + v.y + v.z + v.w;
        s2 += v.x*v.x + v.y*v.y + v.z*v.z + v.w*v.w;
    }
    s  = block_reduce<false>(s,  sh);
    s2 = block_reduce<false>(s2, sh);
    if (threadIdx.x == 0) {
        float mu  = s * (1.f / 16384.f);
        float var = s2 * (1.f / 16384.f) - mu * mu;
        g_mean[bg] = mu;
        g_rstd[bg] = rsqrtf(var + EPSV);
    }
}

__global__ void gn_apply_T_kernel(const float* __restrict__ x,
                                  const float* __restrict__ gamma,
                                  const float* __restrict__ beta) {
    __shared__ float t[32][33];
    int b = blockIdx.z, c0 = blockIdx.y * 32, s0 = blockIdx.x * 32;
    for (int i = threadIdx.y; i < 32; i += 8) {
        int c = c0 + i;
        int bg = b * 32 + (c >> 4);
        float a = g_rstd[bg] * gamma[c];
        float bb = beta[c] - g_mean[bg] * a;
        t[i][threadIdx.x] = x[((long)b * 512 + c) * 1024 + s0 + threadIdx.x] * a + bb;
    }
    __syncthreads();
    for (int i = threadIdx.y; i < 32; i += 8)
        g_xnT[((long)b * 1024 + s0 + i) * 512 + c0 + threadIdx.x] = t[threadIdx.x][i];
}

__global__ void softmax_kernel(float* __restrict__ logits) {
    __shared__ float sh[8];
    long row = blockIdx.x;
    float4* p = (float4*)(logits + row * Sn);
    float4 v = p[threadIdx.x];
    float m = fmaxf(fmaxf(v.x, v.y), fmaxf(v.z, v.w));
    m = block_reduce<true>(m, sh);
    v.x = __expf(v.x - m); v.y = __expf(v.y - m);
    v.z = __expf(v.z - m); v.w = __expf(v.w - m);
    float s = v.x + v.y + v.z + v.w;
    s = block_reduce<false>(s, sh);
    float inv = 1.f / s;
    v.x *= inv; v.y *= inv; v.z *= inv; v.w *= inv;
    p[threadIdx.x] = v;
}

// ---------------------------------------------------------------------------
// Launch
// ---------------------------------------------------------------------------
extern "C" void kernel_launch(void* const* d_in, const int* in_sizes, int n_in,
                              void* d_out, int out_size) {
    const float* x      = (const float*)d_in[0];
    const float* gamma  = (const float*)d_in[1];
    const float* beta   = (const float*)d_in[2];
    const float* w_qkv  = (const float*)d_in[3];
    const float* b_qkv  = (const float*)d_in[4];
    const float* w_proj = (const float*)d_in[5];
    const float* b_proj = (const float*)d_in[6];
    float* out = (float*)d_out;

    float *xnT, *q, *k, *v, *logit, *hT;
    cudaGetSymbolAddress((void**)&xnT,   g_xnT);
    cudaGetSymbolAddress((void**)&q,     g_q);
    cudaGetSymbolAddress((void**)&k,     g_k);
    cudaGetSymbolAddress((void**)&v,     g_v);
    cudaGetSymbolAddress((void**)&logit, g_logit);
    cudaGetSymbolAddress((void**)&hT,    g_hT);

    // dyn smem: max(tiles, stage) + 1024 alignment slack
    const int SM_BIG   = 66560 + 1024;   // BM=BN=128: tiles 64K, stage 66560
    const int SM_SMALL = 49152 + 1024;   // BM=128, BN=64: tiles 48K, stage 33792
    cudaFuncSetAttribute(mma_gemm<128,128,0>, cudaFuncAttributeMaxDynamicSharedMemorySize, SM_BIG);
    cudaFuncSetAttribute(mma_gemm<128,128,1>, cudaFuncAttributeMaxDynamicSharedMemorySize, SM_BIG);
    cudaFuncSetAttribute(mma_gemm<128, 64,2>, cudaFuncAttributeMaxDynamicSharedMemorySize, SM_SMALL);
    cudaFuncSetAttribute(mma_gemm<128,128,3>, cudaFuncAttributeMaxDynamicSharedMemorySize, SM_BIG);

    // 1) GroupNorm + transpose
    gn_stats_kernel<<<Bn * NG, 256>>>(x);
    gn_apply_T_kernel<<<dim3(32, 16, 8), dim3(32, 8)>>>(x, gamma, beta);

    // 2) QKV: D[o, s] = sum_c Wqkv[o,c] * xnT[s,c]  -> scatter to q/k/v
    mma_gemm<128,128,0><<<dim3(8, 12, 8), 256, SM_BIG>>>(
        w_qkv, 512, 0, xnT, 512, 524288, 512, b_qkv, nullptr, q, k, v, 1.f);

    // 3) logits[t, s] = 0.125 * sum_d Q[t,d] K[s,d]
    mma_gemm<128,128,1><<<dim3(8, 8, 64), 256, SM_BIG>>>(
        q, 64, 65536, k, 64, 65536, 64, nullptr, nullptr, logit, nullptr, nullptr, 0.125f);

    // 4) softmax
    softmax_kernel<<<(unsigned)(Bn * NH * Sn), 256>>>(logit);

    // 5) attn[t, d] = sum_s P[t,s] V[d,s]  -> hT (b, t, h*64+d)
    mma_gemm<128,64,2><<<dim3(1, 8, 64), 256, SM_SMALL>>>(
        logit, 1024, 1048576, v, 1024, 65536, 1024, nullptr, nullptr, hT, nullptr, nullptr, 1.f);

    // 6) proj: out[o, s] = sum_c Wp[o,c] hT[s,c] + bias + residual
    mma_gemm<128,128,3><<<dim3(8, 4, 8), 256, SM_BIG>>>(
        w_proj, 512, 0, hT, 512, 524288, 512, b_proj, x, out, nullptr, nullptr, 1.f);
}

// round 5
// speedup vs baseline: 5.1100x; 1.5671x over previous
#include <cuda_runtime.h>
#include <cuda_bf16.h>
#include <cuda_fp16.h>
#include <cstdint>

#define Bn 8
#define Cn 512
#define Sn 1024
#define NH 8
#define NG 32
#define EPSV 1e-5f

// ---------------------------------------------------------------------------
// Static device scratch (allocation-free rule)
// ---------------------------------------------------------------------------
__device__ float  g_xnT[(long)Bn * Sn * Cn];            // (b, s, c) fp32
__device__ __half g_qh[(long)Bn * NH * Sn * 64];        // (bh, t, d) hi
__device__ __half g_ql[(long)Bn * NH * Sn * 64];        // lo
__device__ __half g_kh[(long)Bn * NH * Sn * 64];        // (bh, s, d)
__device__ __half g_kl[(long)Bn * NH * Sn * 64];
__device__ __half g_vh[(long)Bn * NH * 64 * Sn];        // (bh, d, s)
__device__ __half g_vl[(long)Bn * NH * 64 * Sn];
__device__ float  g_hT[(long)Bn * Sn * Cn];             // (b, t, c) fp32
__device__ float  g_mean[Bn * NG];
__device__ float  g_rstd[Bn * NG];

// ---------------------------------------------------------------------------
// PTX helpers (base ISA only)
// ---------------------------------------------------------------------------
__device__ __forceinline__ uint32_t smem_u32(const void* p) {
    uint32_t a;
    asm("{ .reg .u64 t; cvta.to.shared.u64 t, %1; cvt.u32.u64 %0, t; }" : "=r"(a) : "l"(p));
    return a;
}
__device__ __forceinline__ void ldsm4(uint32_t* r, uint32_t addr) {
    asm volatile("ldmatrix.sync.aligned.m8n8.x4.shared.b16 {%0,%1,%2,%3}, [%4];"
        : "=r"(r[0]), "=r"(r[1]), "=r"(r[2]), "=r"(r[3]) : "r"(addr));
}
__device__ __forceinline__ void mma16816(float* c, const uint32_t* a, const uint32_t* b) {
    asm volatile("mma.sync.aligned.m16n8k16.row.col.f32.f16.f16.f32 "
        "{%0,%1,%2,%3}, {%4,%5,%6,%7}, {%8,%9}, {%0,%1,%2,%3};"
        : "+f"(c[0]), "+f"(c[1]), "+f"(c[2]), "+f"(c[3])
        : "r"(a[0]), "r"(a[1]), "r"(a[2]), "r"(a[3]), "r"(b[0]), "r"(b[1]));
}
__device__ __forceinline__ uint32_t packh2(float a, float b) {
    __half2 t = __floats2half2_rn(a, b);
    return *reinterpret_cast<uint32_t*>(&t);
}
#define SWZ(o)    ((o) ^ (((o) >> 3) & 0x70))
#define SWZ256(o) ((o) ^ (((o) >> 4) & 0x70))
#define CP16(d, s)   asm volatile("cp.async.cg.shared.global [%0], [%1], 16;" :: "r"(d), "l"(s) : "memory")
#define CP_COMMIT()  asm volatile("cp.async.commit_group;" ::: "memory")
#define CP_WAIT0()   asm volatile("cp.async.wait_group 0;" ::: "memory")
#define CP_WAIT1()   asm volatile("cp.async.wait_group 1;" ::: "memory")

__device__ __forceinline__ void split_h(float v, __half& h, __half& l) {
    h = __float2half_rn(v);
    l = __float2half_rn(v - __half2float(h));
}

// ---------------------------------------------------------------------------
// Tile loader (fp32 -> fp16 hi/lo, SW128 rows of 64 halfs)
// ---------------------------------------------------------------------------
template<int ROWS>
__device__ __forceinline__ void load_tile(char* hiT, char* loT,
        const float* __restrict__ src, long ld, int r0, int k0, int tid) {
    #pragma unroll
    for (int it = 0; it < ROWS / 16; it++) {
        int idx = it * 256 + tid;
        int row = idx >> 4;
        int k4  = (idx & 15) << 2;
        float4 v = *(const float4*)(src + (long)(r0 + row) * ld + k0 + k4);
        __half2 h0 = __floats2half2_rn(v.x, v.y);
        __half2 h1 = __floats2half2_rn(v.z, v.w);
        float2 f0 = __half22float2(h0), f1 = __half22float2(h1);
        uint2 hi = make_uint2(*reinterpret_cast<uint32_t*>(&h0),
                              *reinterpret_cast<uint32_t*>(&h1));
        uint2 lo = make_uint2(packh2(v.x - f0.x, v.y - f0.y),
                              packh2(v.z - f1.x, v.w - f1.y));
        uint32_t sw = SWZ((uint32_t)row * 128u + (uint32_t)k4 * 2u);
        *reinterpret_cast<uint2*>(hiT + sw) = hi;
        *reinterpret_cast<uint2*>(loT + sw) = lo;
    }
}

// ---------------------------------------------------------------------------
// HMMA GEMM (fp16x3):  D[m,n] = sum_k A[m,k]*B[n,k], both K-major fp32.
// MODE 0: QKV -> scatter into half hi/lo q/k/v tensors (+bias), z=b
// MODE 3: proj (+bias +residual) -> out fp32, z=b
// ---------------------------------------------------------------------------
template<int BM, int BN, int MODE>
__global__ __launch_bounds__(256)
void mma_gemm(const float* __restrict__ A, long ldA, long Az,
              const float* __restrict__ Bp, long ldB, long Bz,
              int K, const float* __restrict__ bias, const float* __restrict__ resid,
              float* __restrict__ OutF,
              __half* __restrict__ H0, __half* __restrict__ H1,
              __half* __restrict__ H2, __half* __restrict__ H3,
              __half* __restrict__ H4, __half* __restrict__ H5)
{
    extern __shared__ char smraw[];
    uint32_t sb = smem_u32(smraw);
    uint32_t aB = (sb + 1023u) & ~1023u;
    char* base = smraw + (aB - sb);
    char* aHi = base;
    char* aLo = base + BM * 128;
    char* bHi = base + 2 * BM * 128;
    char* bLo = bHi + BN * 128;
    uint32_t aHiU = aB, aLoU = aB + BM * 128;
    uint32_t bHiU = aB + 2 * BM * 128, bLoU = bHiU + BN * 128;
    float* stage = (float*)base;

    constexpr int WNT = BN / 4;
    constexpr int NI  = WNT / 8;
    constexpr int NG4 = NI / 2;

    int tid = threadIdx.x, wid = tid >> 5, lane = tid & 31;
    int wm = wid >> 2, wn = wid & 3;
    int m0 = blockIdx.y * BM, n0 = blockIdx.x * BN, z = blockIdx.z;
    const float* Ab = A  + (long)z * Az;
    const float* Bb = Bp + (long)z * Bz;

    float acc[4][NI][4];
    #pragma unroll
    for (int mi = 0; mi < 4; mi++)
        #pragma unroll
        for (int ni = 0; ni < NI; ni++)
            #pragma unroll
            for (int j = 0; j < 4; j++) acc[mi][ni][j] = 0.f;

    int nPass = K >> 6;
    for (int pass = 0; pass < nPass; ++pass) {
        int k0 = pass << 6;
        load_tile<BM>(aHi, aLo, Ab, ldA, m0, k0, tid);
        load_tile<BN>(bHi, bLo, Bb, ldB, n0, k0, tid);
        __syncthreads();

        #pragma unroll
        for (int kc = 0; kc < 4; kc++) {
            uint32_t ah[4][4], al[4][4], bh[NI][2], bl[NI][2];
            #pragma unroll
            for (int mi = 0; mi < 4; mi++) {
                int row = wm * 64 + mi * 16 + (lane & 15);
                uint32_t sw = SWZ((uint32_t)row * 128u + kc * 32u + ((lane >> 4) << 4));
                ldsm4(ah[mi], aHiU + sw);
                ldsm4(al[mi], aLoU + sw);
            }
            #pragma unroll
            for (int g = 0; g < NG4; g++) {
                int nr = wn * WNT + g * 16 + (lane & 7) + ((lane >> 4) & 1) * 8;
                uint32_t sw = SWZ((uint32_t)nr * 128u + kc * 32u + (((lane >> 3) & 1) << 4));
                uint32_t t4[4];
                ldsm4(t4, bHiU + sw);
                bh[g*2][0] = t4[0]; bh[g*2][1] = t4[1];
                bh[g*2+1][0] = t4[2]; bh[g*2+1][1] = t4[3];
                ldsm4(t4, bLoU + sw);
                bl[g*2][0] = t4[0]; bl[g*2][1] = t4[1];
                bl[g*2+1][0] = t4[2]; bl[g*2+1][1] = t4[3];
            }
            #pragma unroll
            for (int mi = 0; mi < 4; mi++)
                #pragma unroll
                for (int ni = 0; ni < NI; ni++) {
                    mma16816(acc[mi][ni], ah[mi], bh[ni]);
                    mma16816(acc[mi][ni], al[mi], bh[ni]);
                    mma16816(acc[mi][ni], ah[mi], bl[ni]);
                }
        }
        __syncthreads();
    }

    constexpr int SLD = BN + 2;
    #pragma unroll
    for (int mi = 0; mi < 4; mi++)
        #pragma unroll
        for (int ni = 0; ni < NI; ni++) {
            int r = wm * 64 + mi * 16 + (lane >> 2);
            int c = wn * WNT + ni * 8 + (lane & 3) * 2;
            *(float2*)&stage[r * SLD + c] = make_float2(acc[mi][ni][0], acc[mi][ni][1]);
            *(float2*)&stage[(r + 8) * SLD + c] = make_float2(acc[mi][ni][2], acc[mi][ni][3]);
        }
    __syncthreads();

    if (MODE == 0) {
        int three = m0 >> 9;
        int b = z;
        if (three < 2) {
            __half* dh = three ? H2 : H0;
            __half* dl = three ? H3 : H1;
            for (int cc = wid; cc < BN; cc += 8) {
                int t = n0 + cc;
                #pragma unroll
                for (int ii = 0; ii < BM / 32; ii++) {
                    int r = lane + 32 * ii;
                    int o = (m0 + r) & 511;
                    int h = o >> 6, d = o & 63;
                    float val = stage[r * SLD + cc] + bias[m0 + r];
                    __half hi, lo; split_h(val, hi, lo);
                    long idx = (((long)(b * 8 + h) << 10) + t) * 64 + d;
                    dh[idx] = hi; dl[idx] = lo;
                }
            }
        } else {
            for (int r = wid; r < BM; r += 8) {
                int o = (m0 + r) & 511;
                int h = o >> 6, d = o & 63;
                float bv = bias[m0 + r];
                long basei = ((long)(b * 8 + h) * 64 + d) * 1024 + n0;
                #pragma unroll
                for (int j = 0; j < BN / 32; j++) {
                    int c = lane + 32 * j;
                    float val = stage[r * SLD + c] + bv;
                    __half hi, lo; split_h(val, hi, lo);
                    H4[basei + c] = hi; H5[basei + c] = lo;
                }
            }
        }
    } else {
        for (int r = wid; r < BM; r += 8) {
            int o = m0 + r;
            float bv = bias[o];
            long basei = (long)z * 524288 + (long)o * 1024 + n0;
            #pragma unroll
            for (int j = 0; j < BN / 32; j++) {
                int c = lane + 32 * j;
                OutF[basei + c] = stage[r * SLD + c] + bv + resid[basei + c];
            }
        }
    }
}

// ---------------------------------------------------------------------------
// Fused flash attention: per CTA = one (bh, 128-row Q tile).
// 8 warps; warp w owns Q rows [w*16, w*16+16). Streams 8 K/V tiles of 128.
// ---------------------------------------------------------------------------
#define SM_QHI 0
#define SM_QLO 16384
#define SM_ST0 32768
#define SM_STG 65536
#define SM_KHI 0
#define SM_KLO 16384
#define SM_VHI 32768
#define SM_VLO 49152

__global__ __launch_bounds__(256)
void attn_kernel(const __half* __restrict__ qh, const __half* __restrict__ ql,
                 const __half* __restrict__ kh, const __half* __restrict__ kl,
                 const __half* __restrict__ vh, const __half* __restrict__ vl,
                 float* __restrict__ hT)
{
    extern __shared__ char smraw[];
    uint32_t sb = smem_u32(smraw);
    uint32_t base = (sb + 1023u) & ~1023u;

    int tid = threadIdx.x, wid = tid >> 5, lane = tid & 31;
    int bh = blockIdx.y;
    int t0 = blockIdx.x * 128;
    int b = bh >> 3, h = bh & 7;

    // ---- prologue: Q + stage0 via cp.async ----
    {
        #pragma unroll
        for (int i = 0; i < 4; i++) {
            int id = tid + i * 256;
            int row = id >> 3, c = id & 7;
            uint32_t sw = SWZ((uint32_t)row * 128u + c * 16u);
            long off = ((long)bh * 1024 + t0 + row) * 64 + c * 8;
            CP16(base + SM_QHI + sw, qh + off);
            CP16(base + SM_QLO + sw, ql + off);
        }
        uint32_t stg = base + SM_ST0;
        #pragma unroll
        for (int i = 0; i < 4; i++) {
            int id = tid + i * 256;
            int row = id >> 3, c = id & 7;
            uint32_t sw = SWZ((uint32_t)row * 128u + c * 16u);
            long off = ((long)bh * 1024 + row) * 64 + c * 8;
            CP16(stg + SM_KHI + sw, kh + off);
            CP16(stg + SM_KLO + sw, kl + off);
        }
        #pragma unroll
        for (int i = 0; i < 4; i++) {
            int id = tid + i * 256;
            int row = id >> 4, c = id & 15;
            uint32_t sw = SWZ256((uint32_t)row * 256u + c * 16u);
            long off = ((long)bh * 64 + row) * 1024 + c * 8;
            CP16(stg + SM_VHI + sw, vh + off);
            CP16(stg + SM_VLO + sw, vl + off);
        }
        CP_COMMIT();
    }

    float m0 = -1e30f, m1 = -1e30f, l0 = 0.f, l1 = 0.f;
    float acc_o[8][4];
    #pragma unroll
    for (int ni = 0; ni < 8; ni++)
        #pragma unroll
        for (int j = 0; j < 4; j++) acc_o[ni][j] = 0.f;

    for (int it = 0; it < 8; it++) {
        if (it < 7) {
            uint32_t stg = base + SM_ST0 + ((it + 1) & 1) * SM_STG;
            int s0 = (it + 1) * 128;
            #pragma unroll
            for (int i = 0; i < 4; i++) {
                int id = tid + i * 256;
                int row = id >> 3, c = id & 7;
                uint32_t sw = SWZ((uint32_t)row * 128u + c * 16u);
                long off = ((long)bh * 1024 + s0 + row) * 64 + c * 8;
                CP16(stg + SM_KHI + sw, kh + off);
                CP16(stg + SM_KLO + sw, kl + off);
            }
            #pragma unroll
            for (int i = 0; i < 4; i++) {
                int id = tid + i * 256;
                int row = id >> 4, c = id & 15;
                uint32_t sw = SWZ256((uint32_t)row * 256u + c * 16u);
                long off = ((long)bh * 64 + row) * 1024 + s0 + c * 8;
                CP16(stg + SM_VHI + sw, vh + off);
                CP16(stg + SM_VLO + sw, vl + off);
            }
            CP_COMMIT();
            CP_WAIT1();
        } else {
            CP_WAIT0();
        }
        __syncthreads();

        uint32_t stg = base + SM_ST0 + (it & 1) * SM_STG;

        // ---- S = Q K^T (fp16x3), 128 cols per warp ----
        float s_acc[16][4];
        #pragma unroll
        for (int ni = 0; ni < 16; ni++)
            #pragma unroll
            for (int j = 0; j < 4; j++) s_acc[ni][j] = 0.f;

        #pragma unroll
        for (int kc = 0; kc < 4; kc++) {
            uint32_t ah[4], al[4];
            {
                int row = wid * 16 + (lane & 15);
                uint32_t sw = SWZ((uint32_t)row * 128u + kc * 32u + ((lane >> 4) << 4));
                ldsm4(ah, base + SM_QHI + sw);
                ldsm4(al, base + SM_QLO + sw);
            }
            #pragma unroll
            for (int g = 0; g < 8; g++) {
                int nr = g * 16 + (lane & 7) + ((lane >> 4) & 1) * 8;
                uint32_t sw = SWZ((uint32_t)nr * 128u + kc * 32u + (((lane >> 3) & 1) << 4));
                uint32_t th[4], tl[4];
                ldsm4(th, stg + SM_KHI + sw);
                ldsm4(tl, stg + SM_KLO + sw);
                mma16816(s_acc[2*g],   ah, th);     // th[0..1]
                mma16816(s_acc[2*g],   al, th);
                mma16816(s_acc[2*g],   ah, tl);
                mma16816(s_acc[2*g+1], ah, th + 2);
                mma16816(s_acc[2*g+1], al, th + 2);
                mma16816(s_acc[2*g+1], ah, tl + 2);
            }
        }

        // ---- online softmax ----
        float mx0 = -1e30f, mx1 = -1e30f;
        #pragma unroll
        for (int ni = 0; ni < 16; ni++) {
            s_acc[ni][0] *= 0.125f; s_acc[ni][1] *= 0.125f;
            s_acc[ni][2] *= 0.125f; s_acc[ni][3] *= 0.125f;
            mx0 = fmaxf(mx0, fmaxf(s_acc[ni][0], s_acc[ni][1]));
            mx1 = fmaxf(mx1, fmaxf(s_acc[ni][2], s_acc[ni][3]));
        }
        mx0 = fmaxf(mx0, __shfl_xor_sync(0xffffffffu, mx0, 1));
        mx0 = fmaxf(mx0, __shfl_xor_sync(0xffffffffu, mx0, 2));
        mx1 = fmaxf(mx1, __shfl_xor_sync(0xffffffffu, mx1, 1));
        mx1 = fmaxf(mx1, __shfl_xor_sync(0xffffffffu, mx1, 2));
        float mn0 = fmaxf(m0, mx0), mn1 = fmaxf(m1, mx1);
        float cr0 = __expf(m0 - mn0), cr1 = __expf(m1 - mn1);
        m0 = mn0; m1 = mn1;
        float sm0 = 0.f, sm1 = 0.f;
        #pragma unroll
        for (int ni = 0; ni < 16; ni++) {
            s_acc[ni][0] = __expf(s_acc[ni][0] - m0);
            s_acc[ni][1] = __expf(s_acc[ni][1] - m0);
            s_acc[ni][2] = __expf(s_acc[ni][2] - m1);
            s_acc[ni][3] = __expf(s_acc[ni][3] - m1);
            sm0 += s_acc[ni][0] + s_acc[ni][1];
            sm1 += s_acc[ni][2] + s_acc[ni][3];
        }
        sm0 += __shfl_xor_sync(0xffffffffu, sm0, 1);
        sm0 += __shfl_xor_sync(0xffffffffu, sm0, 2);
        sm1 += __shfl_xor_sync(0xffffffffu, sm1, 1);
        sm1 += __shfl_xor_sync(0xffffffffu, sm1, 2);
        l0 = l0 * cr0 + sm0;
        l1 = l1 * cr1 + sm1;
        #pragma unroll
        for (int ni = 0; ni < 8; ni++) {
            acc_o[ni][0] *= cr0; acc_o[ni][1] *= cr0;
            acc_o[ni][2] *= cr1; acc_o[ni][3] *= cr1;
        }

        // ---- convert P -> fp16 hi/lo frags ----
        uint32_t phA[16], phB[16], plA[16], plB[16];
        #pragma unroll
        for (int ni = 0; ni < 16; ni++) {
            __half2 hA = __floats2half2_rn(s_acc[ni][0], s_acc[ni][1]);
            __half2 hB = __floats2half2_rn(s_acc[ni][2], s_acc[ni][3]);
            float2 fA = __half22float2(hA), fB = __half22float2(hB);
            phA[ni] = *reinterpret_cast<uint32_t*>(&hA);
            phB[ni] = *reinterpret_cast<uint32_t*>(&hB);
            plA[ni] = packh2(s_acc[ni][0] - fA.x, s_acc[ni][1] - fA.y);
            plB[ni] = packh2(s_acc[ni][2] - fB.x, s_acc[ni][3] - fB.y);
        }

        // ---- O += P V (fp16x3) ----
        #pragma unroll
        for (int kp = 0; kp < 8; kp++) {
            uint32_t pa[4] = { phA[2*kp], phB[2*kp], phA[2*kp+1], phB[2*kp+1] };
            uint32_t pl[4] = { plA[2*kp], plB[2*kp], plA[2*kp+1], plB[2*kp+1] };
            #pragma unroll
            for (int g2 = 0; g2 < 4; g2++) {
                int nr = g2 * 16 + (lane & 7) + ((lane >> 4) & 1) * 8;
                uint32_t sw = SWZ256((uint32_t)nr * 256u + kp * 32u + (((lane >> 3) & 1) << 4));
                uint32_t tv[4], tw[4];
                ldsm4(tv, stg + SM_VHI + sw);
                ldsm4(tw, stg + SM_VLO + sw);
                mma16816(acc_o[2*g2],   pa, tv);
                mma16816(acc_o[2*g2],   pl, tv);
                mma16816(acc_o[2*g2],   pa, tw);
                mma16816(acc_o[2*g2+1], pa, tv + 2);
                mma16816(acc_o[2*g2+1], pl, tv + 2);
                mma16816(acc_o[2*g2+1], pa, tw + 2);
            }
        }
        __syncthreads();
    }

    // ---- epilogue: hT[b, t, h*64+d] = O / l ----
    float inv0 = 1.f / l0, inv1 = 1.f / l1;
    int tr  = t0 + wid * 16 + (lane >> 2);
    #pragma unroll
    for (int ni = 0; ni < 8; ni++) {
        int d0 = ni * 8 + (lane & 3) * 2;
        *(float2*)&hT[((long)b * 1024 + tr) * 512 + h * 64 + d0] =
            make_float2(acc_o[ni][0] * inv0, acc_o[ni][1] * inv0);
        *(float2*)&hT[((long)b * 1024 + tr + 8) * 512 + h * 64 + d0] =
            make_float2(acc_o[ni][2] * inv1, acc_o[ni][3] * inv1);
    }
}

// ---------------------------------------------------------------------------
// Reductions, GroupNorm
// ---------------------------------------------------------------------------
__device__ __forceinline__ float warp_sum(float v) {
    #pragma unroll
    for (int o = 16; o; o >>= 1) v += __shfl_xor_sync(0xffffffffu, v, o);
    return v;
}
__device__ __forceinline__ float block_sum(float v, float* sh) {
    int lane = threadIdx.x & 31, w = threadIdx.x >> 5, nw = blockDim.x >> 5;
    v = warp_sum(v);
    if (lane == 0) sh[w] = v;
    __syncthreads();
    if (w == 0) {
        float r = (lane < nw) ? sh[lane] : 0.f;
        r = warp_sum(r);
        if (lane == 0) sh[0] = r;
    }
    __syncthreads();
    float r = sh[0];
    __syncthreads();
    return r;
}

__global__ void gn_stats_kernel(const float* __restrict__ x) {
    __shared__ float sh[32];
    int bg = blockIdx.x;
    const float4* p = (const float4*)(x + (long)bg * 16384);
    float s = 0.f, s2 = 0.f;
    for (int i = threadIdx.x; i < 4096; i += blockDim.x) {
        float4 v = p[i];
        s  += v.x + v.y + v.z + v.w;
        s2 += v.x*v.x + v.y*v.y + v.z*v.z + v.w*v.w;
    }
    s  = block_sum(s,  sh);
    s2 = block_sum(s2, sh);
    if (threadIdx.x == 0) {
        float mu  = s * (1.f / 16384.f);
        float var = s2 * (1.f / 16384.f) - mu * mu;
        g_mean[bg] = mu;
        g_rstd[bg] = rsqrtf(var + EPSV);
    }
}

__global__ void gn_apply_T_kernel(const float* __restrict__ x,
                                  const float* __restrict__ gamma,
                                  const float* __restrict__ beta) {
    __shared__ float t[32][33];
    int b = blockIdx.z, c0 = blockIdx.y * 32, s0 = blockIdx.x * 32;
    for (int i = threadIdx.y; i < 32; i += 8) {
        int c = c0 + i;
        int bg = b * 32 + (c >> 4);
        float a = g_rstd[bg] * gamma[c];
        float bb = beta[c] - g_mean[bg] * a;
        t[i][threadIdx.x] = x[((long)b * 512 + c) * 1024 + s0 + threadIdx.x] * a + bb;
    }
    __syncthreads();
    for (int i = threadIdx.y; i < 32; i += 8)
        g_xnT[((long)b * 1024 + s0 + i) * 512 + c0 + threadIdx.x] = t[threadIdx.x][i];
}

// ---------------------------------------------------------------------------
// Launch
// ---------------------------------------------------------------------------
extern "C" void kernel_launch(void* const* d_in, const int* in_sizes, int n_in,
                              void* d_out, int out_size) {
    const float* x      = (const float*)d_in[0];
    const float* gamma  = (const float*)d_in[1];
    const float* beta   = (const float*)d_in[2];
    const float* w_qkv  = (const float*)d_in[3];
    const float* b_qkv  = (const float*)d_in[4];
    const float* w_proj = (const float*)d_in[5];
    const float* b_proj = (const float*)d_in[6];
    float* out = (float*)d_out;

    float *xnT, *hT;
    __half *qh, *ql, *kh, *kl, *vh, *vl;
    cudaGetSymbolAddress((void**)&xnT, g_xnT);
    cudaGetSymbolAddress((void**)&hT,  g_hT);
    cudaGetSymbolAddress((void**)&qh,  g_qh);
    cudaGetSymbolAddress((void**)&ql,  g_ql);
    cudaGetSymbolAddress((void**)&kh,  g_kh);
    cudaGetSymbolAddress((void**)&kl,  g_kl);
    cudaGetSymbolAddress((void**)&vh,  g_vh);
    cudaGetSymbolAddress((void**)&vl,  g_vl);

    const int SM_GEMM = 66560 + 1024;
    const int SM_ATTN = 163840 + 1024;
    cudaFuncSetAttribute(mma_gemm<128,128,0>, cudaFuncAttributeMaxDynamicSharedMemorySize, SM_GEMM);
    cudaFuncSetAttribute(mma_gemm<128,128,3>, cudaFuncAttributeMaxDynamicSharedMemorySize, SM_GEMM);
    cudaFuncSetAttribute(attn_kernel,         cudaFuncAttributeMaxDynamicSharedMemorySize, SM_ATTN);

    // 1) GroupNorm + transpose
    gn_stats_kernel<<<Bn * NG, 256>>>(x);
    gn_apply_T_kernel<<<dim3(32, 16, 8), dim3(32, 8)>>>(x, gamma, beta);

    // 2) QKV GEMM -> pre-split fp16 hi/lo q/k/v
    mma_gemm<128,128,0><<<dim3(8, 12, 8), 256, SM_GEMM>>>(
        w_qkv, 512, 0, xnT, 512, 524288, 512, b_qkv, nullptr,
        nullptr, qh, ql, kh, kl, vh, vl);

    // 3) fused flash attention -> hT (b, t, c)
    attn_kernel<<<dim3(8, 64), 256, SM_ATTN>>>(qh, ql, kh, kl, vh, vl, hT);

    // 4) proj GEMM + bias + residual -> out
    mma_gemm<128,128,3><<<dim3(8, 4, 8), 256, SM_GEMM>>>(
        w_proj, 512, 0, hT, 512, 524288, 512, b_proj, x,
        out, nullptr, nullptr, nullptr, nullptr, nullptr, nullptr);
}